// round 1
// baseline (speedup 1.0000x reference)
#include <cuda_runtime.h>
#include <math.h>

#define NN 100000
#define DD 128
#define NE 800000
#define BM 32

// Scratch (allocations are banned; device globals are the sanctioned escape hatch)
__device__ float g_h[NN * DD];      // normalized features
__device__ float g_agg[NN * DD];    // edge-sum accumulator
__device__ float g_deg[NN];         // in-degree (float)
__device__ float g_sum[DD];
__device__ float g_sumsq[DD];

// ---------------------------------------------------------------------------
// Zero the per-iteration accumulators (graph is replayed; must reset each call)
__global__ void k_zero() {
    int idx = blockIdx.x * blockDim.x + threadIdx.x;
    int stride = gridDim.x * blockDim.x;
    float4 z = make_float4(0.f, 0.f, 0.f, 0.f);
    float4* agg4 = reinterpret_cast<float4*>(g_agg);
    const int n4 = NN * DD / 4;
    for (int i = idx; i < n4; i += stride) agg4[i] = z;
    for (int i = idx; i < NN; i += stride) g_deg[i] = 0.f;
    if (idx < DD) { g_sum[idx] = 0.f; g_sumsq[idx] = 0.f; }
}

// ---------------------------------------------------------------------------
// Column sums / sum-of-squares. 128 threads = one column each; rows strided
// across blocks so every 512B row read is fully coalesced.
__global__ void k_stats(const float* __restrict__ feat) {
    int d = threadIdx.x;
    float s = 0.f, s2 = 0.f;
    for (int r = blockIdx.x; r < NN; r += gridDim.x) {
        float v = feat[r * DD + d];
        s += v;
        s2 += v * v;
    }
    atomicAdd(&g_sum[d], s);
    atomicAdd(&g_sumsq[d], s2);
}

// ---------------------------------------------------------------------------
// BatchNorm normalize: h = (x - mean) * rsqrt(var + eps) * gamma + beta
__global__ void k_norm(const float* __restrict__ feat,
                       const float* __restrict__ gamma,
                       const float* __restrict__ beta) {
    int d = threadIdx.x;
    const float invN = 1.f / (float)NN;
    float mean = g_sum[d] * invN;
    float var  = fmaxf(g_sumsq[d] * invN - mean * mean, 0.f);
    float isg  = rsqrtf(var + 1e-5f) * gamma[d];
    float be   = beta[d];
    for (int r = blockIdx.x; r < NN; r += gridDim.x)
        g_h[r * DD + d] = (feat[r * DD + d] - mean) * isg + be;
}

// ---------------------------------------------------------------------------
// Edge aggregation: one warp per edge; each lane reduces a float4 (4 columns)
// into agg[dst] via vector red.global (sm_90+), lane0 counts the degree.
__global__ void k_agg(const int* __restrict__ src, const int* __restrict__ dst) {
    int warp = (blockIdx.x * blockDim.x + threadIdx.x) >> 5;
    int lane = threadIdx.x & 31;
    if (warp >= NE) return;
    int s = src[warp];
    int t = dst[warp];
    const float4* hp = reinterpret_cast<const float4*>(g_h + (size_t)s * DD);
    float4 v = hp[lane];
    float* ap = g_agg + (size_t)t * DD + lane * 4;
    asm volatile("red.global.add.v4.f32 [%0], {%1, %2, %3, %4};"
                 :: "l"(ap), "f"(v.x), "f"(v.y), "f"(v.z), "f"(v.w)
                 : "memory");
    if (lane == 0) atomicAdd(&g_deg[t], 1.f);
}

// ---------------------------------------------------------------------------
// Fused dual-GEMM + bias + skip + exact GELU.
// Persistent CTAs: W_self & W_neigh (128KB) loaded to smem ONCE per CTA,
// then grid-stride over 32-row tiles. 256 threads, each owns a 4x4 micro-tile.
__device__ __forceinline__ float gelu_exact(float x) {
    return 0.5f * x * (1.f + erff(x * 0.70710678118654752f));
}

__global__ void k_gemm(const float* __restrict__ Wself,
                       const float* __restrict__ Wneigh,
                       const float* __restrict__ bias,
                       float* __restrict__ out) {
    extern __shared__ float sm[];
    float* Ws = sm;                    // 128*128
    float* Wn = Ws + DD * DD;          // 128*128
    float* HS = Wn + DD * DD;          // 32*128
    float* HN = HS + BM * DD;          // 32*128
    float* IV = HN + BM * DD;          // 32
    float* BS = IV + BM;               // 128

    int tid = threadIdx.x;             // 256 threads

    // Stage the weight matrices + bias once per CTA
    {
        float4* Ws4 = reinterpret_cast<float4*>(Ws);
        float4* Wn4 = reinterpret_cast<float4*>(Wn);
        const float4* Wsg = reinterpret_cast<const float4*>(Wself);
        const float4* Wng = reinterpret_cast<const float4*>(Wneigh);
        const int nw4 = DD * DD / 4;   // 4096
        for (int i = tid; i < nw4; i += 256) { Ws4[i] = Wsg[i]; Wn4[i] = Wng[i]; }
        if (tid < DD) BS[tid] = bias[tid];
    }
    __syncthreads();

    int tx = tid & 31;                 // column group: cols tx*4 .. tx*4+3
    int ty = tid >> 5;                 // row group:    rows ty*4 .. ty*4+3
    const int ntiles = NN / BM;        // 3125 (exact)

    for (int tile = blockIdx.x; tile < ntiles; tile += gridDim.x) {
        int row0 = tile * BM;

        __syncthreads();               // previous tile's readers done before overwrite
        if (tid < BM) {
            float dg = g_deg[row0 + tid];
            IV[tid] = 1.f / fmaxf(dg, 1.f);
        }
        __syncthreads();

        // Load h-tile and (agg/deg)-tile
        {
            const float4* hg = reinterpret_cast<const float4*>(g_h + (size_t)row0 * DD);
            const float4* ag = reinterpret_cast<const float4*>(g_agg + (size_t)row0 * DD);
            float4* HS4 = reinterpret_cast<float4*>(HS);
            float4* HN4 = reinterpret_cast<float4*>(HN);
#pragma unroll
            for (int i = 0; i < 4; i++) {
                int e = tid + i * 256;          // 0..1023, row = e>>5
                float iv = IV[e >> 5];
                float4 hv = hg[e];
                float4 av = ag[e];
                HS4[e] = hv;
                HN4[e] = make_float4(av.x * iv, av.y * iv, av.z * iv, av.w * iv);
            }
        }
        __syncthreads();

        float acc[4][4];
#pragma unroll
        for (int r = 0; r < 4; r++)
#pragma unroll
            for (int c = 0; c < 4; c++) acc[r][c] = 0.f;

        const float* hrow  = HS + (ty * 4) * DD;
        const float* hnrow = HN + (ty * 4) * DD;

#pragma unroll 4
        for (int k = 0; k < DD; k++) {
            float4 ws = reinterpret_cast<const float4*>(Ws + k * DD)[tx];
            float4 wn = reinterpret_cast<const float4*>(Wn + k * DD)[tx];
#pragma unroll
            for (int r = 0; r < 4; r++) {
                float a  = hrow[r * DD + k];    // broadcast LDS
                float an = hnrow[r * DD + k];   // broadcast LDS
                acc[r][0] += a * ws.x + an * wn.x;
                acc[r][1] += a * ws.y + an * wn.y;
                acc[r][2] += a * ws.z + an * wn.z;
                acc[r][3] += a * ws.w + an * wn.w;
            }
        }

        // Epilogue: + bias + skip(h) then exact GELU
        float4 bv = reinterpret_cast<const float4*>(BS)[tx];
#pragma unroll
        for (int r = 0; r < 4; r++) {
            int row = ty * 4 + r;
            float4 hv = reinterpret_cast<const float4*>(HS + row * DD)[tx];
            float4 o;
            o.x = gelu_exact(acc[r][0] + bv.x + hv.x);
            o.y = gelu_exact(acc[r][1] + bv.y + hv.y);
            o.z = gelu_exact(acc[r][2] + bv.z + hv.z);
            o.w = gelu_exact(acc[r][3] + bv.w + hv.w);
            reinterpret_cast<float4*>(out + (size_t)(row0 + row) * DD)[tx] = o;
        }
    }
}

// ---------------------------------------------------------------------------
extern "C" void kernel_launch(void* const* d_in, const int* in_sizes, int n_in,
                              void* d_out, int out_size) {
    const float* features = (const float*)d_in[0];
    const int*   src      = (const int*)d_in[1];
    const int*   dst      = (const int*)d_in[2];
    const float* gamma    = (const float*)d_in[3];
    const float* beta     = (const float*)d_in[4];
    const float* W_self   = (const float*)d_in[5];
    const float* W_neigh  = (const float*)d_in[6];
    const float* b        = (const float*)d_in[7];
    float* out = (float*)d_out;

    // 164480 bytes of dynamic smem for the GEMM (> default 48KB cap)
    const int GEMM_SMEM = (2 * DD * DD + 2 * BM * DD + BM + DD) * (int)sizeof(float);
    cudaFuncSetAttribute(k_gemm, cudaFuncAttributeMaxDynamicSharedMemorySize, GEMM_SMEM);

    k_zero<<<1024, 256>>>();
    k_stats<<<512, 128>>>(features);
    k_norm<<<512, 128>>>(features, gamma, beta);
    // one warp per edge: 800000 warps / 8 warps per 256-thread block
    k_agg<<<NE / 8, 256>>>(src, dst);
    k_gemm<<<148, 256, GEMM_SMEM>>>(W_self, W_neigh, b, out);
}